// round 4
// baseline (speedup 1.0000x reference)
#include <cuda_runtime.h>
#include <cuda_bf16.h>
#include <cstdint>

// Problem constants (fixed by the dataset)
#define BB 512      // batch
#define TT 512      // timesteps
#define II 128      // sensory inputs
#define UU 64       // LTC units
#define OO 15       // outputs
#define NUNF 4      // ode unfolds
#define LTC_EPS 1e-8f

// ---------------- device scratch (allocation-free rule: __device__ globals) ---------
__device__ float4 g_sparam[II * UU];     // sensory per-synapse {a, b, ce, c}
__device__ float4 g_rparam[UU * UU];     // recurrent per-synapse {a, b, ce, c}
__device__ float  g_sKn[UU], g_sKd[UU];  // sensory constant sums
__device__ float  g_cmt[UU], g_numbase[UU], g_denbase[UU];
__device__ float2 g_wns[BB * TT * UU];   // (w_num_s, w_den_s) per (b,t,u)  ~134MB

// ---------------- helpers ------------------------------------------------------------
__device__ __forceinline__ float tanh_fast(float x) {
    float y;
    asm("tanh.approx.f32 %0, %1;" : "=f"(y) : "f"(x));
    return y;
}
__device__ __forceinline__ float softplus_f(float x) {
    return log1pf(expf(x));
}

// ---------------- kernel 0a: fold parameters (one thread per synapse) -----------------
// sigmoid(z) = 0.5*tanh(z/2) + 0.5
// sensory arg = 0.5*sigma*(x*iw + ib - mu)   -> a = 0.5*sigma*iw, b = 0.5*sigma*(ib - mu)
// s_act = sp(w)*sigmoid = c + c*th, c = 0.5*sp(w); num term uses ce = c*erev
// NOTE: erev is exactly +-1, so c == fabsf(ce); runtime kernels only need {a,b,ce}.
__global__ void fold_params_kernel(
    const float* __restrict__ iw, const float* __restrict__ ib,
    const float* __restrict__ sw, const float* __restrict__ smu,
    const float* __restrict__ ssig, const float* __restrict__ serev,
    const float* __restrict__ w, const float* __restrict__ mu,
    const float* __restrict__ sig, const float* __restrict__ erev)
{
    int idx = blockIdx.x * blockDim.x + threadIdx.x;
    if (idx < II * UU) {
        int i = idx / UU;
        float c  = 0.5f * softplus_f(sw[idx]);
        float ce = c * serev[idx];
        float a  = 0.5f * ssig[idx] * iw[i];
        float b  = 0.5f * ssig[idx] * (ib[i] - smu[idx]);
        g_sparam[idx] = make_float4(a, b, ce, c);
    }
    int r = idx - II * UU;
    if (r >= 0 && r < UU * UU) {
        float c  = 0.5f * softplus_f(w[r]);
        float ce = c * erev[r];
        float a  = 0.5f * sig[r];
        float b  = -0.5f * sig[r] * mu[r];
        g_rparam[r] = make_float4(a, b, ce, c);
    }
}

// ---------------- kernel 0b: per-neuron constant sums ---------------------------------
__global__ void fold_neuron_kernel(
    const float* __restrict__ gleak, const float* __restrict__ vleak,
    const float* __restrict__ cm)
{
    int u = threadIdx.x;
    if (u >= UU) return;

    float kn = 0.f, kd = 0.f;
#pragma unroll 8
    for (int i = 0; i < II; i++) {
        float4 p = g_sparam[i * UU + u];
        kn += p.z; kd += p.w;
    }
    g_sKn[u] = kn;
    g_sKd[u] = kd;

    kn = 0.f; kd = 0.f;
#pragma unroll 8
    for (int j = 0; j < UU; j++) {
        float4 p = g_rparam[j * UU + u];
        kn += p.z; kd += p.w;
    }
    float gp  = softplus_f(gleak[u]);
    float cmt = (float)NUNF * softplus_f(cm[u]);   // sp(cm) / (1/UNFOLDS)
    g_cmt[u]     = cmt;
    g_numbase[u] = gp * vleak[u] + kn;
    g_denbase[u] = cmt + gp + kd + LTC_EPS;
}

// ---------------- kernel 1: sensory synapse sums over all (b,t) ----------------------
// Barrier-free, no smem. 512 threads: u = tid>>3, ig = tid&7 (8 groups of 16 inputs).
// Two rows per iteration -> 32 independent tanh between shuffle tails.
#define ROWS_PER_BLOCK 128
__global__ __launch_bounds__(512, 1) void sensory_kernel(const float* __restrict__ x)
{
    const int tid = threadIdx.x;
    const int u  = tid >> 3;
    const int ig = tid & 7;

    float pa[16], pb[16], pce[16];
#pragma unroll
    for (int ii = 0; ii < 16; ii++) {
        float4 p = g_sparam[(ig * 16 + ii) * UU + u];
        pa[ii] = p.x; pb[ii] = p.y; pce[ii] = p.z;
    }
    const float kn = g_sKn[u];
    const float kd = g_sKd[u];

    const size_t base_row = (size_t)blockIdx.x * ROWS_PER_BLOCK;
    // thread's 16 x values start at column ig*16 -> 4 float4s
    const float4* __restrict__ xr = (const float4*)x + base_row * (II / 4) + ig * 4;

    for (int r = 0; r < ROWS_PER_BLOCK; r += 2) {
        float4 x0[4], x1[4];
#pragma unroll
        for (int q = 0; q < 4; q++) {
            x0[q] = xr[(size_t)r * (II / 4) + q];
            x1[q] = xr[(size_t)(r + 1) * (II / 4) + q];
        }

        float pn0 = 0.f, pd0 = 0.f, pn1 = 0.f, pd1 = 0.f;
#pragma unroll
        for (int q = 0; q < 4; q++) {
            const int s = q * 4;
            const float xv0[4] = {x0[q].x, x0[q].y, x0[q].z, x0[q].w};
            const float xv1[4] = {x1[q].x, x1[q].y, x1[q].z, x1[q].w};
#pragma unroll
            for (int e = 0; e < 4; e++) {
                float t0 = tanh_fast(fmaf(pa[s + e], xv0[e], pb[s + e]));
                float t1 = tanh_fast(fmaf(pa[s + e], xv1[e], pb[s + e]));
                float ce = pce[s + e];
                float c  = fabsf(ce);
                pn0 = fmaf(ce, t0, pn0);  pd0 = fmaf(c, t0, pd0);
                pn1 = fmaf(ce, t1, pn1);  pd1 = fmaf(c, t1, pd1);
            }
        }
#pragma unroll
        for (int o = 1; o <= 4; o <<= 1) {
            pn0 += __shfl_xor_sync(0xffffffffu, pn0, o);
            pn1 += __shfl_xor_sync(0xffffffffu, pn1, o);
            pd0 += __shfl_xor_sync(0xffffffffu, pd0, o);
            pd1 += __shfl_xor_sync(0xffffffffu, pd1, o);
        }
        if (ig == 0) {
            __stcg(&g_wns[(base_row + r) * UU + u],     make_float2(pn0 + kn, pd0 + kd));
            __stcg(&g_wns[(base_row + r + 1) * UU + u], make_float2(pn1 + kn, pd1 + kd));
        }
    }
}

// ---------------- kernel 2: sequential scan + LayerNorm + FC head --------------------
// One block (128 threads = 4 warps) per batch. Thread (u, half) owns half of unit u's
// recurrent synapses (32 params x {a,b,ce} = 96 regs, NO spills). Partner threads are
// adjacent lanes -> one shfl_xor(1) combines the two halves; both lanes then divide
// redundantly so vu stays register-resident (no LDS on the critical path).
__global__ __launch_bounds__(128, 3) void scan_kernel(
    const float* __restrict__ outw, const float* __restrict__ outb,
    const float* __restrict__ lnw,  const float* __restrict__ lnb,
    const float* __restrict__ fcw,  const float* __restrict__ fcb,
    float* __restrict__ out)
{
    __shared__ float4 vsm4[2][UU / 4];
    __shared__ float  stats[2];
    __shared__ float  hbuf[UU];

    const int tid  = threadIdx.x;
    const int u    = tid >> 1;        // 0..63 : unit owned by this thread pair
    const int half = tid & 1;         // which 32 synapses
    const int b    = blockIdx.x;

    float ra[32], rb[32], rce[32];
#pragma unroll
    for (int j = 0; j < 32; j++) {
        float4 p = g_rparam[(half * 32 + j) * UU + u];
        ra[j] = p.x; rb[j] = p.y; rce[j] = p.z;
    }
    const float cmtu = g_cmt[u];
    const float nb   = g_numbase[u];
    const float db   = g_denbase[u];

    if (half == 0) ((float*)vsm4[0])[u] = 0.f;
    float vu = 0.f;
    __syncthreads();

    const float2* __restrict__ wns = g_wns + (size_t)b * TT * UU;
    float2 wnd = __ldcg(&wns[u]);

    for (int t = 0; t < TT; t++) {
        float2 wnd_n = (t + 1 < TT) ? __ldcg(&wns[(t + 1) * UU + u])
                                    : make_float2(0.f, 0.f);
#pragma unroll
        for (int k = 0; k < NUNF; k++) {
            const float4* vr4 = vsm4[k & 1] + half * 8;   // this half's 32 v's
            float pn = 0.f, pd = 0.f;
#pragma unroll
            for (int q = 0; q < 8; q++) {
                float4 v4 = vr4[q];
                const int s = q * 4;
                float t0 = tanh_fast(fmaf(ra[s + 0], v4.x, rb[s + 0]));
                float t1 = tanh_fast(fmaf(ra[s + 1], v4.y, rb[s + 1]));
                float t2 = tanh_fast(fmaf(ra[s + 2], v4.z, rb[s + 2]));
                float t3 = tanh_fast(fmaf(ra[s + 3], v4.w, rb[s + 3]));
                pn = fmaf(rce[s + 0], t0, pn);  pd = fmaf(fabsf(rce[s + 0]), t0, pd);
                pn = fmaf(rce[s + 1], t1, pn);  pd = fmaf(fabsf(rce[s + 1]), t1, pd);
                pn = fmaf(rce[s + 2], t2, pn);  pd = fmaf(fabsf(rce[s + 2]), t2, pd);
                pn = fmaf(rce[s + 3], t3, pn);  pd = fmaf(fabsf(rce[s + 3]), t3, pd);
            }
            pn += __shfl_xor_sync(0xffffffffu, pn, 1);
            pd += __shfl_xor_sync(0xffffffffu, pd, 1);
            float num = fmaf(cmtu, vu, nb) + wnd.x + pn;
            float den = db + wnd.y + pd;
            vu = __fdividef(num, den);
            if (half == 0) ((float*)vsm4[(k & 1) ^ 1])[u] = vu;
            __syncthreads();
        }
        wnd = wnd_n;
    }

    // ----- head: h = v*ow + ob; LayerNorm(eps=1e-5); out = h @ fc_w^T + fc_b -----
    float h = fmaf(vu, outw[u], outb[u]);
    if (half == 0) hbuf[u] = h;
    __syncthreads();
    if (tid < 32) {
        float a = hbuf[tid] + hbuf[tid + 32];
        float q = hbuf[tid] * hbuf[tid] + hbuf[tid + 32] * hbuf[tid + 32];
#pragma unroll
        for (int o = 16; o > 0; o >>= 1) {
            a += __shfl_down_sync(0xffffffffu, a, o);
            q += __shfl_down_sync(0xffffffffu, q, o);
        }
        if (tid == 0) {
            float mean = a * (1.0f / UU);
            float var  = q * (1.0f / UU) - mean * mean;
            stats[0] = mean;
            stats[1] = rsqrtf(var + 1e-5f);
        }
    }
    __syncthreads();
    if (half == 0)
        hbuf[u] = fmaf((h - stats[0]) * stats[1], lnw[u], lnb[u]);
    __syncthreads();
    if (tid < OO) {
        float acc = fcb[tid];
#pragma unroll
        for (int uu = 0; uu < UU; uu++)
            acc = fmaf(hbuf[uu], fcw[tid * UU + uu], acc);
        out[b * OO + tid] = acc;
    }
}

// ---------------- launch --------------------------------------------------------------
extern "C" void kernel_launch(void* const* d_in, const int* in_sizes, int n_in,
                              void* d_out, int out_size)
{
    const float* x     = (const float*)d_in[0];
    const float* iw    = (const float*)d_in[1];
    const float* ibv   = (const float*)d_in[2];
    const float* sw    = (const float*)d_in[3];
    const float* smu   = (const float*)d_in[4];
    const float* ssig  = (const float*)d_in[5];
    const float* serev = (const float*)d_in[6];
    const float* w     = (const float*)d_in[7];
    const float* mu    = (const float*)d_in[8];
    const float* sig   = (const float*)d_in[9];
    const float* erev  = (const float*)d_in[10];
    const float* gleak = (const float*)d_in[11];
    const float* vleak = (const float*)d_in[12];
    const float* cm    = (const float*)d_in[13];
    const float* outw  = (const float*)d_in[14];
    const float* outb  = (const float*)d_in[15];
    const float* lnw   = (const float*)d_in[16];
    const float* lnb   = (const float*)d_in[17];
    const float* fcw   = (const float*)d_in[18];
    const float* fcb   = (const float*)d_in[19];
    float* out = (float*)d_out;

    const int n_syn = II * UU + UU * UU;           // 12288
    fold_params_kernel<<<(n_syn + 255) / 256, 256>>>(iw, ibv, sw, smu, ssig, serev,
                                                     w, mu, sig, erev);
    fold_neuron_kernel<<<1, 64>>>(gleak, vleak, cm);

    int nblocks = (BB * TT) / ROWS_PER_BLOCK;      // 2048
    sensory_kernel<<<nblocks, 512>>>(x);

    scan_kernel<<<BB, 128>>>(outw, outb, lnw, lnb, fcw, fcb, out);
}